// round 1
// baseline (speedup 1.0000x reference)
#include <cuda_runtime.h>
#include <cstdint>

// ---------------------------------------------------------------------------
// TDGSPooling2d: hard Gumbel-softmax 2x2 pooling.
// out[b,c,ho,wo] = x[patch element with max (x/temp + gumbel)] ; gumbel from
// JAX threefry2x32, key=(0,42), partitionable counter layout (bits = o0^o1
// of threefry(0, flat_index)).
// ---------------------------------------------------------------------------

constexpr int B  = 32;
constexpr int C  = 128;
constexpr int H  = 112;
constexpr int W  = 112;
constexpr int Ho = 56;
constexpr int Wo = 56;
constexpr int P    = C * Ho * Wo;   // 401408 outputs per batch
constexpr int NOUT = B * P;         // 12845056
constexpr int XPB  = C * H * W;     // 1605632 x elements per batch

__device__ __forceinline__ unsigned rotl32(unsigned x, int r) {
    return __funnelshift_l(x, x, r);  // single SHF.L.W32
}

// Threefry-2x32, 20 rounds, key = (0, 42). Key-schedule constants folded.
__device__ __forceinline__ uint2 tf2x32_key0_42(unsigned c0, unsigned c1) {
    const unsigned ks1 = 42u;
    const unsigned ks2 = 0x1BD11BDAu ^ 42u;   // ks0 ^ ks1 ^ parity
    unsigned x0 = c0;            // + ks0 (=0)
    unsigned x1 = c1 + ks1;
#define TF_R(r) { x0 += x1; x1 = rotl32(x1, (r)); x1 ^= x0; }
    TF_R(13) TF_R(15) TF_R(26) TF_R(6)
    x0 += ks1; x1 += ks2 + 1u;
    TF_R(17) TF_R(29) TF_R(16) TF_R(24)
    x0 += ks2; x1 += 2u;               // + ks0(0) + 2
    TF_R(13) TF_R(15) TF_R(26) TF_R(6)
    /* x0 += ks0(0) */ x1 += ks1 + 3u;
    TF_R(17) TF_R(29) TF_R(16) TF_R(24)
    x0 += ks1; x1 += ks2 + 4u;
    TF_R(13) TF_R(15) TF_R(26) TF_R(6)
    x0 += ks2; x1 += 5u;               // + ks0(0) + 5
#undef TF_R
    return make_uint2(x0, x1);
}

// JAX uniform(minval=1e-20, maxval=1.0) from 32 random bits, then gumbel.
// Matches: f = bitcast((bits>>9)|0x3F800000) - 1 ; u = max(1e-20, f*1 + 1e-20)
// (XLA folds maxval-minval to 1.0f; fma(f,1,c) == correctly rounded f+c)
__device__ __forceinline__ float gumbel_from_bits(unsigned bits) {
    float f = __uint_as_float((bits >> 9) | 0x3F800000u) - 1.0f;
    float u = fmaxf(1e-20f, fmaf(f, 1.0f, 1e-20f));
    return -logf(-logf(u));   // precise logf == libdevice __nv_logf (XLA path)
}

__global__ __launch_bounds__(256) void tdgs_pool_kernel(
        const float* __restrict__ x,
        const float* __restrict__ temperature,
        float* __restrict__ out) {
    int tid = blockIdx.x * blockDim.x + threadIdx.x;
    if (tid >= NOUT) return;

    // ---- 4 independent threefry hashes (ILP=4) --------------------------
    // flat index into (B,C,Ho,Wo,4) is 4*tid + k ; hi 32 bits of u64 iota = 0
    unsigned base = 4u * (unsigned)tid;
    unsigned bits[4];
#pragma unroll
    for (int k = 0; k < 4; k++) {
        uint2 o = tf2x32_key0_42(0u, base + (unsigned)k);
        bits[k] = o.x ^ o.y;   // partitionable 32-bit fold
    }

    // ---- decode (b,c,ho,wo) ---------------------------------------------
    int b = tid / P;
    int r = tid - b * P;               // c*3136 + ho*56 + wo
    int c = r / (Ho * Wo);
    int s = r - c * (Ho * Wo);
    int ho = s / Wo;
    int wo = s - ho * Wo;

    float t = fmaxf(temperature[r], 0.0f) + 0.1f;   // relu + EPS

    // ---- load 2x2 patch (two aligned float2 loads, coalesced in wo) -----
    const float* xp = x + b * XPB + (c * H + 2 * ho) * W + 2 * wo;
    float2 p0 = *reinterpret_cast<const float2*>(xp);      // row 2ho
    float2 p1 = *reinterpret_cast<const float2*>(xp + W);  // row 2ho+1

    float xv0 = p0.x, xv1 = p0.y, xv2 = p1.x, xv3 = p1.y;

    // ---- argmax of x/temp + g (IEEE div + FADD, mirroring XLA) ----------
    float l0 = xv0 / t + gumbel_from_bits(bits[0]);
    float l1 = xv1 / t + gumbel_from_bits(bits[1]);
    float l2 = xv2 / t + gumbel_from_bits(bits[2]);
    float l3 = xv3 / t + gumbel_from_bits(bits[3]);

    float best_v = l0, best_x = xv0;
    if (l1 > best_v) { best_v = l1; best_x = xv1; }   // strict > == argmax
    if (l2 > best_v) { best_v = l2; best_x = xv2; }   //   first-max-wins
    if (l3 > best_v) { best_v = l3; best_x = xv3; }

    out[tid] = best_x;
}

extern "C" void kernel_launch(void* const* d_in, const int* in_sizes, int n_in,
                              void* d_out, int out_size) {
    const float* x    = (const float*)d_in[0];   // (32,128,112,112) f32
    const float* temp = (const float*)d_in[1];   // (128,56,56) f32
    float* out        = (float*)d_out;           // (32,128,56,56) f32
    (void)in_sizes; (void)n_in; (void)out_size;

    dim3 block(256);
    dim3 grid((NOUT + 255) / 256);               // 50176 blocks, no tail
    tdgs_pool_kernel<<<grid, block>>>(x, temp, out);
}

// round 2
// speedup vs baseline: 1.0902x; 1.0902x over previous
#include <cuda_runtime.h>
#include <cstdint>

// ---------------------------------------------------------------------------
// TDGSPooling2d: hard Gumbel-softmax 2x2 pooling (K=2, stride 2).
// out = x[argmax over patch of (x/temp_relu_eps + gumbel)]
// gumbel bits: JAX threefry2x32, key=(0,42), partitionable (bits = o0^o1 of
// threefry(hi=0, lo=flat_index)).  Fast path uses __logf (MUFU.LG2) with a
// guaranteed error bound; precise logf fallback when argmax margin is unsafe.
// ---------------------------------------------------------------------------

constexpr int B  = 32;
constexpr int C  = 128;
constexpr int H  = 112;
constexpr int W  = 112;
constexpr int Ho = 56;
constexpr int Wo = 56;
constexpr int P    = C * Ho * Wo;   // 401408
constexpr int NOUT = B * P;         // 12845056
constexpr int XPB  = C * H * W;     // 1605632

__device__ __forceinline__ unsigned rotl32(unsigned x, int r) {
    return __funnelshift_l(x, x, r);
}

// Threefry-2x32, 20 rounds, key = (0, 42), constants folded.
__device__ __forceinline__ unsigned tf_fold_key0_42(unsigned c1) {
    const unsigned ks1 = 42u;
    const unsigned ks2 = 0x1BD11BDAu ^ 42u;
    unsigned x0 = 0u;
    unsigned x1 = c1 + ks1;
#define TF_R(r) { x0 += x1; x1 = rotl32(x1, (r)); x1 ^= x0; }
    TF_R(13) TF_R(15) TF_R(26) TF_R(6)
    x0 += ks1; x1 += ks2 + 1u;
    TF_R(17) TF_R(29) TF_R(16) TF_R(24)
    x0 += ks2; x1 += 2u;
    TF_R(13) TF_R(15) TF_R(26) TF_R(6)
    x1 += ks1 + 3u;
    TF_R(17) TF_R(29) TF_R(16) TF_R(24)
    x0 += ks1; x1 += ks2 + 4u;
    TF_R(13) TF_R(15) TF_R(26) TF_R(6)
    x0 += ks2; x1 += 5u;
#undef TF_R
    return x0 ^ x1;   // partitionable 32-bit fold
}

// Precise gumbel — must stay bit-identical to XLA (libdevice logf path).
__device__ __forceinline__ float gumbel_precise(float u) {
    return -logf(-logf(u));
}

__global__ __launch_bounds__(256) void tdgs_pool_kernel(
        const float* __restrict__ x,
        const float* __restrict__ temperature,
        float* __restrict__ out) {
    int tid = blockIdx.x * blockDim.x + threadIdx.x;
    if (tid >= NOUT) return;

    // ---- 4 independent threefry hashes (ILP=4) --------------------------
    unsigned base = 4u * (unsigned)tid;
    unsigned bits[4];
#pragma unroll
    for (int k = 0; k < 4; k++) bits[k] = tf_fold_key0_42(base + (unsigned)k);

    // ---- decode (b,c,ho,wo) ---------------------------------------------
    int b = tid / P;
    int r = tid - b * P;
    int c = r / (Ho * Wo);
    int s = r - c * (Ho * Wo);
    int ho = s / Wo;
    int wo = s - ho * Wo;

    float t = fmaxf(temperature[r], 0.0f) + 0.1f;   // relu + EPS

    const float* xp = x + b * XPB + (c * H + 2 * ho) * W + 2 * wo;
    float2 p0 = *reinterpret_cast<const float2*>(xp);
    float2 p1 = *reinterpret_cast<const float2*>(xp + W);
    float xv0 = p0.x, xv1 = p0.y, xv2 = p1.x, xv3 = p1.y;

    // ---- per-draw uniform + exact logits prefix -------------------------
    float uu[4], qq[4], xv[4] = {xv0, xv1, xv2, xv3};
    float lf[4], ee[4];
#pragma unroll
    for (int k = 0; k < 4; k++) {
        float f = __uint_as_float((bits[k] >> 9) | 0x3F800000u) - 1.0f;
        float u = fmaxf(1e-20f, fmaf(f, 1.0f, 1e-20f));   // == XLA uniform
        uu[k] = u;
        float q = xv[k] / t;                              // IEEE div (== XLA)
        qq[k] = q;
        // fast gumbel: 2x MUFU.LG2 instead of 2x precise logf polynomials
        float y = -__logf(u);                             // in [1.19e-7, 46.1]
        float g = -__logf(y);
        lf[k] = q + g;
        // conservative bound on |fast_l - precise_l|:
        //   inner abs+rel error a(1+y), amplified by 1/y through outer log,
        //   plus outer abs+rel error a(1+|g|), plus add rounding. a<=5e-7.
        ee[k] = 3e-6f + 2e-6f * fabsf(g) + __fdividef(2e-6f, y);
    }

    // ---- fast argmax (first-max-wins) -----------------------------------
    float bl = lf[0], bx = xv[0], be = ee[0];
    if (lf[1] > bl) { bl = lf[1]; bx = xv[1]; be = ee[1]; }
    if (lf[2] > bl) { bl = lf[2]; bx = xv[2]; be = ee[2]; }
    if (lf[3] > bl) { bl = lf[3]; bx = xv[3]; be = ee[3]; }

    // safety: exactly one candidate (the winner itself) may sit within the
    // combined error band of the max; otherwise the precise argmax could
    // differ -> recompute precisely.
    int cnt = 0;
#pragma unroll
    for (int k = 0; k < 4; k++)
        cnt += (bl - lf[k] <= be + ee[k]) ? 1 : 0;

    if (cnt != 1) {
        // ---- precise fallback (bit-identical to XLA logits) -------------
        float l0 = qq[0] + gumbel_precise(uu[0]);
        float l1 = qq[1] + gumbel_precise(uu[1]);
        float l2 = qq[2] + gumbel_precise(uu[2]);
        float l3 = qq[3] + gumbel_precise(uu[3]);
        float bv = l0; bx = xv[0];
        if (l1 > bv) { bv = l1; bx = xv[1]; }
        if (l2 > bv) { bv = l2; bx = xv[2]; }
        if (l3 > bv) { bv = l3; bx = xv[3]; }
    }

    out[tid] = bx;
}

extern "C" void kernel_launch(void* const* d_in, const int* in_sizes, int n_in,
                              void* d_out, int out_size) {
    const float* x    = (const float*)d_in[0];   // (32,128,112,112) f32
    const float* temp = (const float*)d_in[1];   // (128,56,56) f32
    float* out        = (float*)d_out;           // (32,128,56,56) f32
    (void)in_sizes; (void)n_in; (void)out_size;

    tdgs_pool_kernel<<<(NOUT + 255) / 256, 256>>>(x, temp, out);
}

// round 3
// speedup vs baseline: 1.1043x; 1.0129x over previous
#include <cuda_runtime.h>
#include <cstdint>

// ---------------------------------------------------------------------------
// TDGSPooling2d: hard Gumbel-softmax 2x2 pooling (K=2, stride 2).
// out = x[argmax over patch of (x/temp_relu_eps + gumbel)]
// gumbel bits: JAX threefry2x32, key=(0,42), partitionable (bits = o0^o1 of
// threefry(hi=0, lo=flat_index)).
// Fast path: rcp.approx + __log2f with certified error bound; precise
// (IEEE div + libdevice logf) fallback when the argmax margin is unsafe.
// Each thread computes TWO adjacent outputs (wo, wo+1): 8-way hash ILP,
// float4 x loads, amortized index decode.
// ---------------------------------------------------------------------------

constexpr int B  = 32;
constexpr int C  = 128;
constexpr int H  = 112;
constexpr int W  = 112;
constexpr int Ho = 56;
constexpr int Wo = 56;
constexpr int P    = C * Ho * Wo;   // 401408
constexpr int NOUT = B * P;         // 12845056
constexpr int NTHR = NOUT / 2;      // 6422528
constexpr int XPB  = C * H * W;     // 1605632

__device__ __forceinline__ unsigned rotl32(unsigned x, int r) {
    return __funnelshift_l(x, x, r);
}

// Threefry-2x32, 20 rounds, key = (0, 42), constants folded, fold o0^o1.
__device__ __forceinline__ unsigned tf_fold_key0_42(unsigned c1) {
    const unsigned ks1 = 42u;
    const unsigned ks2 = 0x1BD11BDAu ^ 42u;
    unsigned x0 = 0u;
    unsigned x1 = c1 + ks1;
#define TF_R(r) { x0 += x1; x1 = rotl32(x1, (r)); x1 ^= x0; }
    TF_R(13) TF_R(15) TF_R(26) TF_R(6)
    x0 += ks1; x1 += ks2 + 1u;
    TF_R(17) TF_R(29) TF_R(16) TF_R(24)
    x0 += ks2; x1 += 2u;
    TF_R(13) TF_R(15) TF_R(26) TF_R(6)
    x1 += ks1 + 3u;
    TF_R(17) TF_R(29) TF_R(16) TF_R(24)
    x0 += ks1; x1 += ks2 + 4u;
    TF_R(13) TF_R(15) TF_R(26) TF_R(6)
    x0 += ks2; x1 += 5u;
#undef TF_R
    return x0 ^ x1;
}

__device__ __forceinline__ float rcp_approx(float a) {
    float r;
    asm("rcp.approx.f32 %0, %1;" : "=f"(r) : "f"(a));
    return r;
}

// One output: argmax over 4 (x/t + gumbel). Fast path with certified bound,
// precise fallback bit-identical to XLA.
__device__ __forceinline__ float pool_one(float xv0, float xv1, float xv2,
                                          float xv3, float t,
                                          const unsigned* bits) {
    const float xv[4] = {xv0, xv1, xv2, xv3};
    float rcpt = rcp_approx(t);          // t >= 0.1, always normal

    float uu[4], lf[4], ee[4];
#pragma unroll
    for (int k = 0; k < 4; k++) {
        // uniform: f = bitcast((bits>>9)|0x3F800000)-1 ; u = max(1e-20, f+1e-20)
        unsigned m = __umulhi(bits[k], 1u << 23) + 0x3F800000u; // == (>>9)|exp
        float f = __uint_as_float(m) - 1.0f;
        float u = fmaxf(1e-20f, f + 1e-20f);
        uu[k] = u;
        // fast gumbel via raw lg2 (MUFU): y = -ln(u), g = -ln(y)
        float y = __log2f(u) * -0.69314718056f;   // y in [1.19e-7, 46.1]
        float g = __log2f(y) * -0.69314718056f;
        float q = xv[k] * rcpt;                   // approx x/t
        lf[k] = q + g;
        // certified |fast - precise| bound (>=2x slack on every term):
        float ry = rcp_approx(y);
        ee[k] = fmaf(2e-6f, fabsf(g),
                fmaf(2e-6f, ry,
                fmaf(5e-7f, fabsf(q), 3.2e-6f)));
    }

    // first-max-wins argmax (matches jnp.argmax tie rule)
    float bl = lf[0], bx = xv[0], be = ee[0];
    if (lf[1] > bl) { bl = lf[1]; bx = xv[1]; be = ee[1]; }
    if (lf[2] > bl) { bl = lf[2]; bx = xv[2]; be = ee[2]; }
    if (lf[3] > bl) { bl = lf[3]; bx = xv[3]; be = ee[3]; }

    // guard: only the winner may sit inside the combined error band
    int cnt = 0;
#pragma unroll
    for (int k = 0; k < 4; k++)
        cnt += (bl - lf[k] <= be + ee[k]) ? 1 : 0;

    if (cnt != 1) {
        // precise path: IEEE div + libdevice logf — bit-identical to XLA
        float l0 = xv[0] / t + (-logf(-logf(uu[0])));
        float l1 = xv[1] / t + (-logf(-logf(uu[1])));
        float l2 = xv[2] / t + (-logf(-logf(uu[2])));
        float l3 = xv[3] / t + (-logf(-logf(uu[3])));
        float bv = l0; bx = xv[0];
        if (l1 > bv) { bv = l1; bx = xv[1]; }
        if (l2 > bv) { bv = l2; bx = xv[2]; }
        if (l3 > bv) { bv = l3; bx = xv[3]; }
    }
    return bx;
}

__global__ __launch_bounds__(256) void tdgs_pool_kernel(
        const float* __restrict__ x,
        const float* __restrict__ temperature,
        float* __restrict__ out) {
    int idx = blockIdx.x * blockDim.x + threadIdx.x;
    if (idx >= NTHR) return;
    int tid2 = idx * 2;                 // first of the output pair

    // ---- 8 independent threefry hashes (ILP=8) --------------------------
    unsigned basec = 8u * (unsigned)idx;   // = 4*tid2
    unsigned bits[8];
#pragma unroll
    for (int j = 0; j < 8; j++) bits[j] = tf_fold_key0_42(basec + (unsigned)j);

    // ---- decode (b,c,ho,wo) for the pair (wo even, pair shares b,c,ho) --
    int b = tid2 / P;
    int r = tid2 - b * P;
    int c = r / (Ho * Wo);
    int s = r - c * (Ho * Wo);
    int ho = s / Wo;
    int wo = s - ho * Wo;               // even

    float2 t2 = *reinterpret_cast<const float2*>(temperature + r);
    float t0 = fmaxf(t2.x, 0.0f) + 0.1f;
    float t1 = fmaxf(t2.y, 0.0f) + 0.1f;

    const float* xp = x + b * XPB + (c * H + 2 * ho) * W + 2 * wo;
    float4 row0 = *reinterpret_cast<const float4*>(xp);      // row 2ho
    float4 row1 = *reinterpret_cast<const float4*>(xp + W);  // row 2ho+1

    float o0 = pool_one(row0.x, row0.y, row1.x, row1.y, t0, bits);
    float o1 = pool_one(row0.z, row0.w, row1.z, row1.w, t1, bits + 4);

    *reinterpret_cast<float2*>(out + tid2) = make_float2(o0, o1);
}

extern "C" void kernel_launch(void* const* d_in, const int* in_sizes, int n_in,
                              void* d_out, int out_size) {
    const float* x    = (const float*)d_in[0];   // (32,128,112,112) f32
    const float* temp = (const float*)d_in[1];   // (128,56,56) f32
    float* out        = (float*)d_out;           // (32,128,56,56) f32
    (void)in_sizes; (void)n_in; (void)out_size;

    tdgs_pool_kernel<<<(NTHR + 255) / 256, 256>>>(x, temp, out);
}

// round 4
// speedup vs baseline: 1.1383x; 1.0308x over previous
#include <cuda_runtime.h>
#include <cstdint>

// ---------------------------------------------------------------------------
// TDGSPooling2d: hard Gumbel-softmax 2x2 pooling (K=2, stride 2).
// out = x[argmax over patch of (x/temp_relu_eps + gumbel)]
// gumbel bits: JAX threefry2x32, key=(0,42), partitionable (bits = o0^o1 of
// threefry(hi=0, lo=flat_index)).
// Pipe balancing: ALL threefry adds are forced to IMAD (fma pipe) via
// mad.lo.u32 with an opaque kernel-parameter multiplier 'one' -- the alu
// pipe keeps only the irreducible SHF+LOP3 hash ops.
// Fast math path: rcp.approx + __log2f with certified error bound; precise
// (IEEE div + libdevice logf) fallback when the argmax margin is unsafe.
// ---------------------------------------------------------------------------

constexpr int B  = 32;
constexpr int C  = 128;
constexpr int H  = 112;
constexpr int W  = 112;
constexpr int Ho = 56;
constexpr int Wo = 56;
constexpr int P    = C * Ho * Wo;   // 401408
constexpr int NOUT = B * P;         // 12845056
constexpr int NTHR = NOUT / 2;      // 6422528 == 25088 * 256 (no tail)
constexpr int XPB  = C * H * W;     // 1605632

__device__ __forceinline__ unsigned rotl32(unsigned x, int r) {
    return __funnelshift_l(x, x, r);          // SHF (alu)
}

// d = a*one + c  -> IMAD on the fma pipe ('one' is an opaque runtime 1)
__device__ __forceinline__ unsigned mad1(unsigned a, unsigned one, unsigned c) {
    unsigned d;
    asm("mad.lo.u32 %0, %1, %2, %3;" : "=r"(d) : "r"(a), "r"(one), "r"(c));
    return d;
}
// d = one*imm + c  -> IMAD (imm multiplier) on the fma pipe
#define MAD1I(one, imm, c) ({                                   \
    unsigned d_;                                                \
    asm("mad.lo.u32 %0, %1, %2, %3;"                            \
        : "=r"(d_) : "r"(one), "n"(imm), "r"(c));               \
    d_; })

// Threefry-2x32, 20 rounds, key = (0, 42), constants folded, fold o0^o1.
__device__ __forceinline__ unsigned tf_fold_key0_42(unsigned c1, unsigned one) {
    const unsigned ks1 = 42u;
    const unsigned ks2 = 0x1BD11BDAu ^ 42u;
    unsigned x0 = 0u;
    unsigned x1 = MAD1I(one, 42u, c1);
#define TF_R(r) { x0 = mad1(x1, one, x0); x1 = rotl32(x1, (r)); x1 ^= x0; }
    TF_R(13) TF_R(15) TF_R(26) TF_R(6)
    x0 = MAD1I(one, ks1, x0);        x1 = MAD1I(one, (ks2 + 1u), x1);
    TF_R(17) TF_R(29) TF_R(16) TF_R(24)
    x0 = MAD1I(one, ks2, x0);        x1 = MAD1I(one, 2u, x1);
    TF_R(13) TF_R(15) TF_R(26) TF_R(6)
    /* x0 += 0 */                    x1 = MAD1I(one, (ks1 + 3u), x1);
    TF_R(17) TF_R(29) TF_R(16) TF_R(24)
    x0 = MAD1I(one, ks1, x0);        x1 = MAD1I(one, (ks2 + 4u), x1);
    TF_R(13) TF_R(15) TF_R(26) TF_R(6)
    x0 = MAD1I(one, ks2, x0);        x1 = MAD1I(one, 5u, x1);
#undef TF_R
    return x0 ^ x1;
}

__device__ __forceinline__ float rcp_approx(float a) {
    float r;
    asm("rcp.approx.f32 %0, %1;" : "=f"(r) : "f"(a));
    return r;
}

// One output: argmax over 4 of (x/t + gumbel). Fast path with certified
// bound; precise fallback bit-identical to XLA.
__device__ __forceinline__ float pool_one(float xv0, float xv1, float xv2,
                                          float xv3, float t,
                                          const unsigned* bits) {
    const float xv[4] = {xv0, xv1, xv2, xv3};
    float rcpt = rcp_approx(t);          // t >= 0.1, always normal

    float uu[4], lf[4], ee[4];
#pragma unroll
    for (int k = 0; k < 4; k++) {
        // uniform: f = bitcast((bits>>9)|0x3F800000)-1 ; u = max(1e-20, f+1e-20)
        // (>>9)|exp done as IMAD.HI + IADD-able add; fmax dropped: f>=0 so
        // fl(f+1e-20) >= 1e-20 by rounding monotonicity -> identical value.
        unsigned m = __umulhi(bits[k], 1u << 23) + 0x3F800000u;
        float f = __uint_as_float(m) - 1.0f;
        float u = f + 1e-20f;                     // == XLA uniform, exactly
        uu[k] = u;
        // fast gumbel via MUFU.LG2: y = -ln(u), g = -ln(y)
        float y = __log2f(u) * -0.69314718056f;   // y in [1.19e-7, 46.1]
        float g = __log2f(y) * -0.69314718056f;
        float q = xv[k] * rcpt;                   // approx x/t
        lf[k] = q + g;
        // certified |fast - precise| bound (>=2x slack on every term)
        float ry = rcp_approx(y);
        ee[k] = fmaf(2e-6f, fabsf(g),
                fmaf(2e-6f, ry,
                fmaf(5e-7f, fabsf(q), 3.2e-6f)));
    }

    // first-max-wins argmax (matches jnp.argmax tie rule)
    float bl = lf[0], bx = xv[0], be = ee[0];
    if (lf[1] > bl) { bl = lf[1]; bx = xv[1]; be = ee[1]; }
    if (lf[2] > bl) { bl = lf[2]; bx = xv[2]; be = ee[2]; }
    if (lf[3] > bl) { bl = lf[3]; bx = xv[3]; be = ee[3]; }

    // guard: only the winner may sit inside the combined error band
    int cnt = 0;
#pragma unroll
    for (int k = 0; k < 4; k++)
        cnt += (bl - lf[k] <= be + ee[k]) ? 1 : 0;

    if (cnt != 1) {
        // precise path: IEEE div + libdevice logf -- bit-identical to XLA
        float l0 = xv[0] / t + (-logf(-logf(uu[0])));
        float l1 = xv[1] / t + (-logf(-logf(uu[1])));
        float l2 = xv[2] / t + (-logf(-logf(uu[2])));
        float l3 = xv[3] / t + (-logf(-logf(uu[3])));
        float bv = l0; bx = xv[0];
        if (l1 > bv) { bv = l1; bx = xv[1]; }
        if (l2 > bv) { bv = l2; bx = xv[2]; }
        if (l3 > bv) { bv = l3; bx = xv[3]; }
    }
    return bx;
}

__global__ __launch_bounds__(256) void tdgs_pool_kernel(
        const float* __restrict__ x,
        const float* __restrict__ temperature,
        float* __restrict__ out,
        unsigned one) {                 // opaque 1 (defeats const-prop)
    int idx = blockIdx.x * blockDim.x + threadIdx.x;   // grid exact, no tail
    int tid2 = idx * 2;                 // first of the output pair

    // ---- 8 independent threefry hashes (ILP=8) --------------------------
    unsigned basec = 8u * (unsigned)idx;   // = 4*tid2
    unsigned bits[8];
#pragma unroll
    for (int j = 0; j < 8; j++)
        bits[j] = tf_fold_key0_42(basec + (unsigned)j, one);

    // ---- decode (b,c,ho,wo) for the pair (wo even, pair shares b,c,ho) --
    int b = tid2 / P;
    int r = tid2 - b * P;
    int c = r / (Ho * Wo);
    int s = r - c * (Ho * Wo);
    int ho = s / Wo;
    int wo = s - ho * Wo;               // even

    float2 t2 = *reinterpret_cast<const float2*>(temperature + r);
    float t0 = fmaxf(t2.x, 0.0f) + 0.1f;
    float t1 = fmaxf(t2.y, 0.0f) + 0.1f;

    const float* xp = x + b * XPB + (c * H + 2 * ho) * W + 2 * wo;
    float4 row0 = *reinterpret_cast<const float4*>(xp);      // row 2ho
    float4 row1 = *reinterpret_cast<const float4*>(xp + W);  // row 2ho+1

    float o0 = pool_one(row0.x, row0.y, row1.x, row1.y, t0, bits);
    float o1 = pool_one(row0.z, row0.w, row1.z, row1.w, t1, bits + 4);

    *reinterpret_cast<float2*>(out + tid2) = make_float2(o0, o1);
}

extern "C" void kernel_launch(void* const* d_in, const int* in_sizes, int n_in,
                              void* d_out, int out_size) {
    const float* x    = (const float*)d_in[0];   // (32,128,112,112) f32
    const float* temp = (const float*)d_in[1];   // (128,56,56) f32
    float* out        = (float*)d_out;           // (32,128,56,56) f32
    (void)in_sizes; (void)n_in; (void)out_size;

    tdgs_pool_kernel<<<NTHR / 256, 256>>>(x, temp, out, 1u);
}